// round 8
// baseline (speedup 1.0000x reference)
#include <cuda_runtime.h>
#include <cuda_bf16.h>
#include <math.h>
#include <stdint.h>

#define VOCAB   100000
#define EMB     256
#define NS      256
#define BATCH   16384

// ---------------------------------------------------------------------------
// Device globals (static scratch — no runtime allocation)
// ---------------------------------------------------------------------------
__device__ float          g_scratch[BATCH * EMB];   // fallback embed buffer
__device__ __nv_bfloat16  g_sw[NS * EMB];           // bf16 sampled weights (GEMM B)
__device__ float          g_adj[NS];                // bias - log(NS*prob) per sample
__device__ float          g_partial[BATCH / 128];   // per-block loss partials

// ---------------------------------------------------------------------------
// Helpers
// ---------------------------------------------------------------------------
__device__ __forceinline__ uint32_t smem_to_u32(const void* p)
{
    uint32_t a;
    asm("{ .reg .u64 t; cvta.to.shared.u64 t, %1; cvt.u32.u64 %0, t; }"
        : "=r"(a) : "l"(p));
    return a;
}

// jnp int64 silently becomes int32 unless x64 enabled; detect per block.
// If truly int64 (ids < 2^31), all odd 32-bit words are zero.
__device__ __forceinline__ int detect_is64(const int* ids)
{
    int is64 = 1;
    #pragma unroll
    for (int k = 0; k < 16; k++)
        if (ids[2 * k + 1] != 0) { is64 = 0; break; }
    return is64;
}

__device__ __forceinline__ int load_id(const void* p, int i, int is64)
{
    if (is64) return (int)((const long long*)p)[i];
    return ((const int*)p)[i];
}

__device__ __forceinline__ float log_uniform_adj(int id)
{
    const float inv_log_range = 1.0f / logf((float)VOCAB + 1.0f);
    float lp = (logf((float)id + 2.0f) - logf((float)id + 1.0f)) * inv_log_range;
    return logf((float)NS * lp);
}

// softplus(x) = xent(x, label=0); softplus(-x) = xent(x, label=1)
__device__ __forceinline__ float softplus0(float x)
{
    return fmaxf(x, 0.0f) + log1pf(expf(-fabsf(x)));
}

#define LDSM_X4(r0, r1, r2, r3, addr) \
    asm volatile("ldmatrix.sync.aligned.m8n8.x4.shared.b16 {%0,%1,%2,%3}, [%4];" \
                 : "=r"(r0), "=r"(r1), "=r"(r2), "=r"(r3) : "r"(addr))

// ---------------------------------------------------------------------------
// Kernel 1: gather sampled weight rows -> bf16 g_sw, plus adjustment terms.
// One block per sampled id, 64 threads.
// ---------------------------------------------------------------------------
__global__ void prep_sampled_kernel(const float* __restrict__ nce_w,
                                    const float* __restrict__ nce_b,
                                    const void*  __restrict__ sids)
{
    __shared__ int sh64;
    int row = blockIdx.x;
    int t   = threadIdx.x;
    if (t == 0) sh64 = detect_is64((const int*)sids);
    __syncthreads();
    int id = load_id(sids, row, sh64);

    float4 v = ((const float4*)(nce_w + (size_t)id * EMB))[t];
    __nv_bfloat162 p0 = __floats2bfloat162_rn(v.x, v.y);
    __nv_bfloat162 p1 = __floats2bfloat162_rn(v.z, v.w);
    uint2 packed; packed.x = *(uint32_t*)&p0; packed.y = *(uint32_t*)&p1;
    ((uint2*)(g_sw + (size_t)row * EMB))[t] = packed;

    if (t == 0)
        g_adj[row] = nce_b[id] - log_uniform_adj(id);
}

// ---------------------------------------------------------------------------
// Kernel 2 (fused): per block of 128 batch rows —
//   a) gather embed rows: fp32 -> d_out (output #1), bf16 -> smem A tile
//   b) true-label logits + xent (fp32, exact)
//   c) 128x256x256 bf16 mma.sync GEMM vs smem-resident B (ldmatrix frags)
//   d) softplus epilogue + per-row sum + block reduce -> g_partial
// 512 threads = 16 warps (4x4), warp tile 32x64, m16n8k16.
// ---------------------------------------------------------------------------
#define KPAD   264                 // bf16 row stride: 528B -> conflict-free LDSM
#define SM_IDS  0                  // 128 int
#define SM_LAB  512                // 128 int
#define SM_ADJ  1024               // 256 f32
#define SM_ROWX 2048               // 128 f32 (true xent per row)
#define SM_RED  2560               // 128*4 f32
#define SM_RED2 4608               // 128 f32
#define SM_FLAG 5120               // is64
#define SM_A    5632               // 128*264 bf16 = 67584
#define SM_B    73216              // 256*264 bf16 = 135168
#define SM_TOT  208896

__global__ void __launch_bounds__(512)
fused_main_kernel(const float* __restrict__ embeddings,
                  const float* __restrict__ nce_w,
                  const float* __restrict__ nce_b,
                  const void*  __restrict__ inputs,
                  const void*  __restrict__ labels,
                  float*       __restrict__ d_out,
                  int use_dout)
{
    extern __shared__ char smem[];
    uint32_t sb = smem_to_u32(smem);
    int*   s_ids = (int*)(smem + SM_IDS);
    int*   s_lab = (int*)(smem + SM_LAB);
    float* adjs  = (float*)(smem + SM_ADJ);
    float* rowx  = (float*)(smem + SM_ROWX);
    float* red   = (float*)(smem + SM_RED);
    float* red2  = (float*)(smem + SM_RED2);

    const int t    = threadIdx.x;
    const int wid  = t >> 5;
    const int lane = t & 31;
    const int rb   = blockIdx.x * 128;

    float* embed_out = use_dout ? d_out : g_scratch;

    // ---- dtype detect + id staging ----
    if (t == 0) *(int*)(smem + SM_FLAG) = detect_is64((const int*)inputs);
    __syncthreads();
    const int is64 = *(const int*)(smem + SM_FLAG);
    if (t < 128) {
        s_ids[t] = load_id(inputs, rb + t, is64);
        s_lab[t] = load_id(labels, rb + t, is64);
    }
    if (t < NS) adjs[t] = g_adj[t];
    __syncthreads();

    // ---- load B: 256x256 bf16 -> smem (8192 uint4, 16/thread) ----
    {
        const uint4* src = (const uint4*)g_sw;
        #pragma unroll
        for (int i = 0; i < 16; i++) {
            int idx = t + 512 * i;
            int r = idx >> 5, c = idx & 31;
            *(uint4*)(smem + SM_B + r * 528 + c * 16) = src[idx];
        }
    }

    // ---- gather + true-label xent: warp w handles rows w*8 .. w*8+7 ----
    {
        #pragma unroll
        for (int i = 0; i < 8; i++) {
            int r_loc = wid * 8 + i;
            int id  = s_ids[r_loc];
            int lab = s_lab[r_loc];

            const float4* e4 = (const float4*)(embeddings + (size_t)id  * EMB);
            const float4* w4 = (const float4*)(nce_w      + (size_t)lab * EMB);
            float4* o4 = (float4*)(embed_out + (size_t)(rb + r_loc) * EMB);

            float4 a0 = e4[lane];
            float4 a1 = e4[lane + 32];
            float4 b0 = w4[lane];
            float4 b1 = w4[lane + 32];
            o4[lane]      = a0;
            o4[lane + 32] = a1;

            __nv_bfloat162 p0 = __floats2bfloat162_rn(a0.x, a0.y);
            __nv_bfloat162 p1 = __floats2bfloat162_rn(a0.z, a0.w);
            __nv_bfloat162 p2 = __floats2bfloat162_rn(a1.x, a1.y);
            __nv_bfloat162 p3 = __floats2bfloat162_rn(a1.z, a1.w);
            uint2 v0; v0.x = *(uint32_t*)&p0; v0.y = *(uint32_t*)&p1;
            uint2 v1; v1.x = *(uint32_t*)&p2; v1.y = *(uint32_t*)&p3;
            *(uint2*)(smem + SM_A + r_loc * 528 + lane * 8)       = v0;
            *(uint2*)(smem + SM_A + r_loc * 528 + 256 + lane * 8) = v1;

            float p = a0.x * b0.x + a0.y * b0.y + a0.z * b0.z + a0.w * b0.w
                    + a1.x * b1.x + a1.y * b1.y + a1.z * b1.z + a1.w * b1.w;
            #pragma unroll
            for (int o = 16; o > 0; o >>= 1)
                p += __shfl_xor_sync(0xffffffffu, p, o);
            if (lane == 0) {
                float x = p + nce_b[lab] - log_uniform_adj(lab);
                rowx[r_loc] = softplus0(-x);   // label = 1
            }
        }
    }
    __syncthreads();

    // ---- GEMM: warp tile 32(m) x 64(n), 16 k-steps, ldmatrix fragments ----
    const int warp_m = (wid >> 2) * 32;
    const int warp_n = (wid & 3) * 64;
    const int group  = lane >> 2;
    const int tig    = lane & 3;

    float c[2][8][4];
    #pragma unroll
    for (int mt = 0; mt < 2; mt++)
        #pragma unroll
        for (int nt = 0; nt < 8; nt++)
            #pragma unroll
            for (int q = 0; q < 4; q++) c[mt][nt][q] = 0.0f;

    // ldmatrix lane-address bases (bytes)
    const uint32_t aA = sb + SM_A
        + (uint32_t)((warp_m + (lane & 15)) * 528 + (lane >> 4) * 16);
    const uint32_t aB = sb + SM_B
        + (uint32_t)((warp_n + ((lane >> 4) * 8) + (lane & 7)) * 528
                     + (((lane >> 3) & 1) * 16));

    #pragma unroll
    for (int kk = 0; kk < 16; kk++) {
        const uint32_t kb = kk * 32;   // 16 bf16 = 32 bytes
        uint32_t a[2][4], b[8][2];
        #pragma unroll
        for (int mt = 0; mt < 2; mt++)
            LDSM_X4(a[mt][0], a[mt][1], a[mt][2], a[mt][3],
                    aA + mt * 16 * 528 + kb);
        #pragma unroll
        for (int p = 0; p < 4; p++)
            LDSM_X4(b[2*p][0], b[2*p][1], b[2*p+1][0], b[2*p+1][1],
                    aB + p * 16 * 528 + kb);
        #pragma unroll
        for (int mt = 0; mt < 2; mt++)
            #pragma unroll
            for (int nt = 0; nt < 8; nt++)
                asm volatile(
                    "mma.sync.aligned.m16n8k16.row.col.f32.bf16.bf16.f32 "
                    "{%0,%1,%2,%3}, {%4,%5,%6,%7}, {%8,%9}, {%0,%1,%2,%3};"
                    : "+f"(c[mt][nt][0]), "+f"(c[mt][nt][1]),
                      "+f"(c[mt][nt][2]), "+f"(c[mt][nt][3])
                    : "r"(a[mt][0]), "r"(a[mt][1]), "r"(a[mt][2]), "r"(a[mt][3]),
                      "r"(b[nt][0]), "r"(b[nt][1]));
    }

    // ---- epilogue: softplus + row sums ----
    float rs[2][2] = {{0.f, 0.f}, {0.f, 0.f}};
    #pragma unroll
    for (int mt = 0; mt < 2; mt++) {
        #pragma unroll
        for (int nt = 0; nt < 8; nt++) {
            int n0 = warp_n + nt * 8 + tig * 2;
            float adj0 = adjs[n0], adj1 = adjs[n0 + 1];
            rs[mt][0] += softplus0(c[mt][nt][0] + adj0)
                       + softplus0(c[mt][nt][1] + adj1);
            rs[mt][1] += softplus0(c[mt][nt][2] + adj0)
                       + softplus0(c[mt][nt][3] + adj1);
        }
    }
    #pragma unroll
    for (int mt = 0; mt < 2; mt++)
        #pragma unroll
        for (int h = 0; h < 2; h++) {
            rs[mt][h] += __shfl_xor_sync(0xffffffffu, rs[mt][h], 1);
            rs[mt][h] += __shfl_xor_sync(0xffffffffu, rs[mt][h], 2);
        }
    if (tig == 0) {
        int wc = wid & 3;
        red[(warp_m + group)      * 4 + wc] = rs[0][0];
        red[(warp_m + group + 8)  * 4 + wc] = rs[0][1];
        red[(warp_m + group + 16) * 4 + wc] = rs[1][0];
        red[(warp_m + group + 24) * 4 + wc] = rs[1][1];
    }
    __syncthreads();

    if (t < 128)
        red2[t] = red[t * 4] + red[t * 4 + 1] + red[t * 4 + 2] + red[t * 4 + 3]
                + rowx[t];
    __syncthreads();
    #pragma unroll
    for (int o = 64; o > 0; o >>= 1) {
        if (t < o) red2[t] += red2[t + o];
        __syncthreads();
    }
    if (t == 0) g_partial[blockIdx.x] = red2[0];
}

// ---------------------------------------------------------------------------
// Kernel 3: sum 128 block partials -> mean cost
// ---------------------------------------------------------------------------
__global__ void reduce_cost_kernel(float* __restrict__ d_out, int out_idx)
{
    __shared__ float sm[128];
    int t = threadIdx.x;
    sm[t] = g_partial[t];
    __syncthreads();
    #pragma unroll
    for (int o = 64; o > 0; o >>= 1) {
        if (t < o) sm[t] += sm[t + o];
        __syncthreads();
    }
    if (t == 0) d_out[out_idx] = sm[0] / (float)BATCH;
}

// ---------------------------------------------------------------------------
// Launch
// ---------------------------------------------------------------------------
extern "C" void kernel_launch(void* const* d_in, const int* in_sizes, int n_in,
                              void* d_out, int out_size)
{
    const float* embeddings = (const float*)d_in[0];
    const float* nce_w      = (const float*)d_in[1];
    const float* nce_b      = (const float*)d_in[2];
    const void*  inputs     = d_in[3];
    const void*  labels     = d_in[4];
    const void*  sids       = d_in[5];
    float*       out        = (float*)d_out;

    int use_dout = (out_size >= BATCH * EMB + 1) ? 1 : 0;

    static int smem_set = 0;
    if (!smem_set) {
        cudaFuncSetAttribute(fused_main_kernel,
                             cudaFuncAttributeMaxDynamicSharedMemorySize,
                             SM_TOT);
        smem_set = 1;
    }

    prep_sampled_kernel<<<NS, 64>>>(nce_w, nce_b, sids);

    fused_main_kernel<<<BATCH / 128, 512, SM_TOT>>>(embeddings, nce_w, nce_b,
                                                    inputs, labels, out,
                                                    use_dout);

    reduce_cost_kernel<<<1, 128>>>(out, out_size - 1);
}

// round 9
// speedup vs baseline: 1.4953x; 1.4953x over previous
#include <cuda_runtime.h>
#include <cuda_bf16.h>
#include <math.h>
#include <stdint.h>

#define VOCAB   100000
#define EMB     256
#define NS      256
#define BATCH   16384

// ---------------------------------------------------------------------------
// Device globals (static scratch — no runtime allocation)
// ---------------------------------------------------------------------------
__device__ float          g_rowsum[BATCH];          // true-label xent per row
__device__ float          g_scratch[BATCH * EMB];   // fallback embed buffer
__device__ __nv_bfloat16  g_embed_bf[BATCH * EMB];  // bf16 embed (GEMM A)
__device__ __nv_bfloat16  g_sw[NS * EMB];           // bf16 sampled weights (GEMM B)
__device__ float          g_adj[NS];                // bias - log(NS*prob)
__device__ float          g_partial[BATCH / 128];   // per-block loss partials

// ---------------------------------------------------------------------------
// Helpers
// ---------------------------------------------------------------------------
__device__ __forceinline__ uint32_t smem_to_u32(const void* p)
{
    uint32_t a;
    asm("{ .reg .u64 t; cvta.to.shared.u64 t, %1; cvt.u32.u64 %0, t; }"
        : "=r"(a) : "l"(p));
    return a;
}

// jnp int64 silently becomes int32 unless x64 enabled; detect cheaply.
__device__ __forceinline__ int detect_is64(const int* ids)
{
    int is64 = 1;
    #pragma unroll
    for (int k = 0; k < 16; k++)
        if (ids[2 * k + 1] != 0) { is64 = 0; break; }
    return is64;
}

__device__ __forceinline__ int load_id(const void* p, int i, int is64)
{
    if (is64) return (int)((const long long*)p)[i];
    return ((const int*)p)[i];
}

__device__ __forceinline__ float log_uniform_adj(int id)
{
    const float inv_log_range = 1.0f / logf((float)VOCAB + 1.0f);
    float lp = (logf((float)id + 2.0f) - logf((float)id + 1.0f)) * inv_log_range;
    return logf((float)NS * lp);
}

// softplus(x) = xent(x, label=0); softplus(-x) = xent(x, label=1)
__device__ __forceinline__ float softplus0(float x)
{
    return fmaxf(x, 0.0f) + log1pf(expf(-fabsf(x)));
}

#define LDSM_X4(r0, r1, r2, r3, addr) \
    asm volatile("ldmatrix.sync.aligned.m8n8.x4.shared.b16 {%0,%1,%2,%3}, [%4];" \
                 : "=r"(r0), "=r"(r1), "=r"(r2), "=r"(r3) : "r"(addr))

// ---------------------------------------------------------------------------
// Kernel 1: gather embed rows (fp32 -> d_out, bf16 -> g_embed_bf)
//           + true-label logits + true xent.  One warp per batch row.
// ---------------------------------------------------------------------------
__global__ void gather_true_kernel(const float* __restrict__ embeddings,
                                   const float* __restrict__ nce_w,
                                   const float* __restrict__ nce_b,
                                   const void*  __restrict__ inputs,
                                   const void*  __restrict__ labels,
                                   float*       __restrict__ d_out,
                                   int use_dout)
{
    __shared__ int sh64;
    if (threadIdx.x == 0) sh64 = detect_is64((const int*)inputs);
    __syncthreads();
    const int is64 = sh64;

    int warp = (blockIdx.x * blockDim.x + threadIdx.x) >> 5;
    int lane = threadIdx.x & 31;
    if (warp >= BATCH) return;

    float* embed_out = use_dout ? d_out : g_scratch;

    int id  = load_id(inputs, warp, is64);
    int lab = load_id(labels, warp, is64);

    const float4* e4 = (const float4*)(embeddings + (size_t)id  * EMB);
    const float4* w4 = (const float4*)(nce_w      + (size_t)lab * EMB);
    float4*       o4 = (float4*)(embed_out + (size_t)warp * EMB);

    float4 a0 = e4[lane];
    float4 a1 = e4[lane + 32];
    float4 b0 = w4[lane];
    float4 b1 = w4[lane + 32];
    o4[lane]      = a0;
    o4[lane + 32] = a1;

    {
        __nv_bfloat162 p0 = __floats2bfloat162_rn(a0.x, a0.y);
        __nv_bfloat162 p1 = __floats2bfloat162_rn(a0.z, a0.w);
        __nv_bfloat162 p2 = __floats2bfloat162_rn(a1.x, a1.y);
        __nv_bfloat162 p3 = __floats2bfloat162_rn(a1.z, a1.w);
        uint2* dst = (uint2*)(g_embed_bf + (size_t)warp * EMB);
        uint2 v0; v0.x = *(uint32_t*)&p0; v0.y = *(uint32_t*)&p1;
        uint2 v1; v1.x = *(uint32_t*)&p2; v1.y = *(uint32_t*)&p3;
        dst[lane]      = v0;
        dst[lane + 32] = v1;
    }

    float p = a0.x * b0.x + a0.y * b0.y + a0.z * b0.z + a0.w * b0.w
            + a1.x * b1.x + a1.y * b1.y + a1.z * b1.z + a1.w * b1.w;
    #pragma unroll
    for (int o = 16; o > 0; o >>= 1)
        p += __shfl_xor_sync(0xffffffffu, p, o);

    if (lane == 0) {
        float x = p + nce_b[lab] - log_uniform_adj(lab);
        g_rowsum[warp] = softplus0(-x);   // label = 1
    }
}

// ---------------------------------------------------------------------------
// Kernel 1b: gather sampled weight rows -> bf16 g_sw + adjustment terms.
// 32 blocks x 256 threads, one warp per sampled row.
// ---------------------------------------------------------------------------
__global__ void prep_sampled_kernel(const float* __restrict__ nce_w,
                                    const float* __restrict__ nce_b,
                                    const void*  __restrict__ sids)
{
    __shared__ int sh64;
    if (threadIdx.x == 0) sh64 = detect_is64((const int*)sids);
    __syncthreads();
    const int is64 = sh64;

    int row  = blockIdx.x * 8 + (threadIdx.x >> 5);
    int lane = threadIdx.x & 31;
    int id   = load_id(sids, row, is64);

    const float4* w4 = (const float4*)(nce_w + (size_t)id * EMB);
    float4 v0 = w4[lane];
    float4 v1 = w4[lane + 32];

    __nv_bfloat162 p0 = __floats2bfloat162_rn(v0.x, v0.y);
    __nv_bfloat162 p1 = __floats2bfloat162_rn(v0.z, v0.w);
    __nv_bfloat162 p2 = __floats2bfloat162_rn(v1.x, v1.y);
    __nv_bfloat162 p3 = __floats2bfloat162_rn(v1.z, v1.w);
    uint2* dst = (uint2*)(g_sw + (size_t)row * EMB);
    uint2 a; a.x = *(uint32_t*)&p0; a.y = *(uint32_t*)&p1;
    uint2 b; b.x = *(uint32_t*)&p2; b.y = *(uint32_t*)&p3;
    dst[lane]      = a;
    dst[lane + 32] = b;

    if (lane == 0)
        g_adj[row] = nce_b[id] - log_uniform_adj(id);
}

// ---------------------------------------------------------------------------
// Kernel 2: bf16 mma.sync GEMM 16384x256 @ (256x256)^T, ldmatrix fragments,
// fused softplus epilogue + row sums + block reduce.
// Block: 128 rows x 256 cols, 512 threads = 16 warps (4x4), warp tile 32x64.
// ---------------------------------------------------------------------------
#define SM_ADJ  0                  // 256 f32
#define SM_RED  1024               // 128*4 f32
#define SM_RED2 3072               // 128 f32
#define SM_A    4096               // 128 rows * 528B = 67584
#define SM_B    71680              // 256 rows * 528B = 135168
#define SM_TOT  206848

__global__ void __launch_bounds__(512)
sampled_gemm_kernel(float* __restrict__ dummy)
{
    extern __shared__ char smem[];
    uint32_t sb = smem_to_u32(smem);
    float* adjs = (float*)(smem + SM_ADJ);
    float* red  = (float*)(smem + SM_RED);
    float* red2 = (float*)(smem + SM_RED2);

    const int t    = threadIdx.x;
    const int wid  = t >> 5;
    const int lane = t & 31;
    const int rb   = blockIdx.x * 128;

    // ---- load A tile: 4096 uint4 (8/thread) ----
    {
        const uint4* src = (const uint4*)(g_embed_bf + (size_t)rb * EMB);
        #pragma unroll
        for (int i = 0; i < 8; i++) {
            int idx = t + 512 * i;
            int r = idx >> 5, c = idx & 31;
            *(uint4*)(smem + SM_A + r * 528 + c * 16) = src[idx];
        }
    }
    // ---- load B: 8192 uint4 (16/thread) ----
    {
        const uint4* src = (const uint4*)g_sw;
        #pragma unroll
        for (int i = 0; i < 16; i++) {
            int idx = t + 512 * i;
            int r = idx >> 5, c = idx & 31;
            *(uint4*)(smem + SM_B + r * 528 + c * 16) = src[idx];
        }
    }
    if (t < NS) adjs[t] = g_adj[t];
    __syncthreads();

    // ---- GEMM mainloop: warp tile 32(m) x 64(n), 16 k-steps ----
    const int warp_m = (wid >> 2) * 32;
    const int warp_n = (wid & 3) * 64;
    const int group  = lane >> 2;
    const int tig    = lane & 3;

    float c[2][8][4];
    #pragma unroll
    for (int mt = 0; mt < 2; mt++)
        #pragma unroll
        for (int nt = 0; nt < 8; nt++)
            #pragma unroll
            for (int q = 0; q < 4; q++) c[mt][nt][q] = 0.0f;

    // ldmatrix lane-address bases (validated in round 8)
    const uint32_t aA = sb + SM_A
        + (uint32_t)((warp_m + (lane & 15)) * 528 + (lane >> 4) * 16);
    const uint32_t aB = sb + SM_B
        + (uint32_t)((warp_n + ((lane >> 4) * 8) + (lane & 7)) * 528
                     + (((lane >> 3) & 1) * 16));

    #pragma unroll
    for (int kk = 0; kk < 16; kk++) {
        const uint32_t kb = kk * 32;   // 16 bf16 = 32 bytes
        uint32_t a[2][4], b[8][2];
        #pragma unroll
        for (int mt = 0; mt < 2; mt++)
            LDSM_X4(a[mt][0], a[mt][1], a[mt][2], a[mt][3],
                    aA + mt * 16 * 528 + kb);
        #pragma unroll
        for (int p = 0; p < 4; p++)
            LDSM_X4(b[2*p][0], b[2*p][1], b[2*p+1][0], b[2*p+1][1],
                    aB + p * 16 * 528 + kb);
        #pragma unroll
        for (int mt = 0; mt < 2; mt++)
            #pragma unroll
            for (int nt = 0; nt < 8; nt++)
                asm volatile(
                    "mma.sync.aligned.m16n8k16.row.col.f32.bf16.bf16.f32 "
                    "{%0,%1,%2,%3}, {%4,%5,%6,%7}, {%8,%9}, {%0,%1,%2,%3};"
                    : "+f"(c[mt][nt][0]), "+f"(c[mt][nt][1]),
                      "+f"(c[mt][nt][2]), "+f"(c[mt][nt][3])
                    : "r"(a[mt][0]), "r"(a[mt][1]), "r"(a[mt][2]), "r"(a[mt][3]),
                      "r"(b[nt][0]), "r"(b[nt][1]));
    }

    // ---- epilogue: softplus + row sums ----
    float rs[2][2] = {{0.f, 0.f}, {0.f, 0.f}};
    #pragma unroll
    for (int mt = 0; mt < 2; mt++) {
        #pragma unroll
        for (int nt = 0; nt < 8; nt++) {
            int n0 = warp_n + nt * 8 + tig * 2;
            float adj0 = adjs[n0], adj1 = adjs[n0 + 1];
            rs[mt][0] += softplus0(c[mt][nt][0] + adj0)
                       + softplus0(c[mt][nt][1] + adj1);
            rs[mt][1] += softplus0(c[mt][nt][2] + adj0)
                       + softplus0(c[mt][nt][3] + adj1);
        }
    }
    #pragma unroll
    for (int mt = 0; mt < 2; mt++)
        #pragma unroll
        for (int h = 0; h < 2; h++) {
            rs[mt][h] += __shfl_xor_sync(0xffffffffu, rs[mt][h], 1);
            rs[mt][h] += __shfl_xor_sync(0xffffffffu, rs[mt][h], 2);
        }
    if (tig == 0) {
        int wc = wid & 3;
        red[(warp_m + group)      * 4 + wc] = rs[0][0];
        red[(warp_m + group + 8)  * 4 + wc] = rs[0][1];
        red[(warp_m + group + 16) * 4 + wc] = rs[1][0];
        red[(warp_m + group + 24) * 4 + wc] = rs[1][1];
    }
    __syncthreads();

    if (t < 128)
        red2[t] = red[t * 4] + red[t * 4 + 1] + red[t * 4 + 2] + red[t * 4 + 3]
                + g_rowsum[rb + t];
    __syncthreads();
    #pragma unroll
    for (int o = 64; o > 0; o >>= 1) {
        if (t < o) red2[t] += red2[t + o];
        __syncthreads();
    }
    if (t == 0) g_partial[blockIdx.x] = red2[0];
}

// ---------------------------------------------------------------------------
// Kernel 3: sum 128 block partials -> mean cost
// ---------------------------------------------------------------------------
__global__ void reduce_cost_kernel(float* __restrict__ d_out, int out_idx)
{
    __shared__ float sm[128];
    int t = threadIdx.x;
    sm[t] = g_partial[t];
    __syncthreads();
    #pragma unroll
    for (int o = 64; o > 0; o >>= 1) {
        if (t < o) sm[t] += sm[t + o];
        __syncthreads();
    }
    if (t == 0) d_out[out_idx] = sm[0] / (float)BATCH;
}

// ---------------------------------------------------------------------------
// Launch
// ---------------------------------------------------------------------------
extern "C" void kernel_launch(void* const* d_in, const int* in_sizes, int n_in,
                              void* d_out, int out_size)
{
    const float* embeddings = (const float*)d_in[0];
    const float* nce_w      = (const float*)d_in[1];
    const float* nce_b      = (const float*)d_in[2];
    const void*  inputs     = d_in[3];
    const void*  labels     = d_in[4];
    const void*  sids       = d_in[5];
    float*       out        = (float*)d_out;

    int use_dout = (out_size >= BATCH * EMB + 1) ? 1 : 0;

    static int smem_set = 0;
    if (!smem_set) {
        cudaFuncSetAttribute(sampled_gemm_kernel,
                             cudaFuncAttributeMaxDynamicSharedMemorySize,
                             SM_TOT);
        smem_set = 1;
    }

    prep_sampled_kernel<<<NS / 8, 256>>>(nce_w, nce_b, sids);

    gather_true_kernel<<<BATCH / 8, 256>>>(embeddings, nce_w, nce_b,
                                           inputs, labels, out, use_dout);

    sampled_gemm_kernel<<<BATCH / 128, 512, SM_TOT>>>(out);

    reduce_cost_kernel<<<1, 128>>>(out, out_size - 1);
}

// round 10
// speedup vs baseline: 1.5292x; 1.0226x over previous
#include <cuda_runtime.h>
#include <cuda_bf16.h>
#include <math.h>
#include <stdint.h>

#define VOCAB   100000
#define EMB     256
#define NS      256
#define BATCH   16384

// ---------------------------------------------------------------------------
// Device globals (static scratch — no runtime allocation)
// ---------------------------------------------------------------------------
__device__ float          g_rowsum[BATCH];          // true-label xent per row
__device__ float          g_scratch[BATCH * EMB];   // fallback embed buffer
__device__ __nv_bfloat16  g_embed_bf[BATCH * EMB];  // bf16 embed (GEMM A)
__device__ __nv_bfloat16  g_sw[NS * EMB];           // bf16 sampled weights (GEMM B)
__device__ float          g_adj[NS];                // bias - log(NS*prob)
__device__ float          g_partial[BATCH / 128];   // per-block loss partials
__device__ unsigned int   g_ticket;                 // last-block election (self-reset)

// ---------------------------------------------------------------------------
// Helpers
// ---------------------------------------------------------------------------
__device__ __forceinline__ uint32_t smem_to_u32(const void* p)
{
    uint32_t a;
    asm("{ .reg .u64 t; cvta.to.shared.u64 t, %1; cvt.u32.u64 %0, t; }"
        : "=r"(a) : "l"(p));
    return a;
}

// jnp int64 silently becomes int32 unless x64 enabled; detect cheaply.
__device__ __forceinline__ int detect_is64(const int* ids)
{
    int is64 = 1;
    #pragma unroll
    for (int k = 0; k < 16; k++)
        if (ids[2 * k + 1] != 0) { is64 = 0; break; }
    return is64;
}

__device__ __forceinline__ int load_id(const void* p, int i, int is64)
{
    if (is64) return (int)((const long long*)p)[i];
    return ((const int*)p)[i];
}

__device__ __forceinline__ float log_uniform_adj(int id)
{
    const float inv_log_range = 1.0f / logf((float)VOCAB + 1.0f);
    float lp = (logf((float)id + 2.0f) - logf((float)id + 1.0f)) * inv_log_range;
    return logf((float)NS * lp);
}

// softplus(x) = xent(x, label=0); softplus(-x) = xent(x, label=1)
__device__ __forceinline__ float softplus0(float x)
{
    return fmaxf(x, 0.0f) + log1pf(expf(-fabsf(x)));
}

#define LDSM_X4(r0, r1, r2, r3, addr) \
    asm volatile("ldmatrix.sync.aligned.m8n8.x4.shared.b16 {%0,%1,%2,%3}, [%4];" \
                 : "=r"(r0), "=r"(r1), "=r"(r2), "=r"(r3) : "r"(addr))

// ---------------------------------------------------------------------------
// Kernel 1 (combined): blocks [0, 2048) gather embed rows + true-label xent;
// blocks [2048, 2080) prep sampled weights (bf16) + adjustment terms.
// 256 threads, one warp per row in both branches.
// ---------------------------------------------------------------------------
#define GATHER_BLOCKS (BATCH / 8)        // 2048
#define PREP_BLOCKS   (NS / 8)           // 32

__global__ void gather_prep_kernel(const float* __restrict__ embeddings,
                                   const float* __restrict__ nce_w,
                                   const float* __restrict__ nce_b,
                                   const void*  __restrict__ inputs,
                                   const void*  __restrict__ labels,
                                   const void*  __restrict__ sids,
                                   float*       __restrict__ d_out,
                                   int use_dout)
{
    const int lane = threadIdx.x & 31;

    if (blockIdx.x >= GATHER_BLOCKS) {
        // ---------------- prep branch: sampled weights -> bf16 + adj --------
        __shared__ int sh64p;
        if (threadIdx.x == 0) sh64p = detect_is64((const int*)sids);
        __syncthreads();
        int row = (blockIdx.x - GATHER_BLOCKS) * 8 + (threadIdx.x >> 5);
        int id  = load_id(sids, row, sh64p);

        const float4* w4 = (const float4*)(nce_w + (size_t)id * EMB);
        float4 v0 = w4[lane];
        float4 v1 = w4[lane + 32];

        __nv_bfloat162 p0 = __floats2bfloat162_rn(v0.x, v0.y);
        __nv_bfloat162 p1 = __floats2bfloat162_rn(v0.z, v0.w);
        __nv_bfloat162 p2 = __floats2bfloat162_rn(v1.x, v1.y);
        __nv_bfloat162 p3 = __floats2bfloat162_rn(v1.z, v1.w);
        uint2* dst = (uint2*)(g_sw + (size_t)row * EMB);
        uint2 a; a.x = *(uint32_t*)&p0; a.y = *(uint32_t*)&p1;
        uint2 b; b.x = *(uint32_t*)&p2; b.y = *(uint32_t*)&p3;
        dst[lane]      = a;
        dst[lane + 32] = b;

        if (lane == 0)
            g_adj[row] = nce_b[id] - log_uniform_adj(id);
        return;
    }

    // ---------------- gather branch ----------------------------------------
    __shared__ int sh64;
    if (threadIdx.x == 0) sh64 = detect_is64((const int*)inputs);
    __syncthreads();
    const int is64 = sh64;

    int warp = (blockIdx.x * blockDim.x + threadIdx.x) >> 5;

    float* embed_out = use_dout ? d_out : g_scratch;

    int id  = load_id(inputs, warp, is64);
    int lab = load_id(labels, warp, is64);

    const float4* e4 = (const float4*)(embeddings + (size_t)id  * EMB);
    const float4* w4 = (const float4*)(nce_w      + (size_t)lab * EMB);
    float4*       o4 = (float4*)(embed_out + (size_t)warp * EMB);

    float4 a0 = e4[lane];
    float4 a1 = e4[lane + 32];
    float4 b0 = w4[lane];
    float4 b1 = w4[lane + 32];
    o4[lane]      = a0;
    o4[lane + 32] = a1;

    {
        __nv_bfloat162 p0 = __floats2bfloat162_rn(a0.x, a0.y);
        __nv_bfloat162 p1 = __floats2bfloat162_rn(a0.z, a0.w);
        __nv_bfloat162 p2 = __floats2bfloat162_rn(a1.x, a1.y);
        __nv_bfloat162 p3 = __floats2bfloat162_rn(a1.z, a1.w);
        uint2* dst = (uint2*)(g_embed_bf + (size_t)warp * EMB);
        uint2 v0; v0.x = *(uint32_t*)&p0; v0.y = *(uint32_t*)&p1;
        uint2 v1; v1.x = *(uint32_t*)&p2; v1.y = *(uint32_t*)&p3;
        dst[lane]      = v0;
        dst[lane + 32] = v1;
    }

    float p = a0.x * b0.x + a0.y * b0.y + a0.z * b0.z + a0.w * b0.w
            + a1.x * b1.x + a1.y * b1.y + a1.z * b1.z + a1.w * b1.w;
    #pragma unroll
    for (int o = 16; o > 0; o >>= 1)
        p += __shfl_xor_sync(0xffffffffu, p, o);

    if (lane == 0) {
        float x = p + nce_b[lab] - log_uniform_adj(lab);
        g_rowsum[warp] = softplus0(-x);   // label = 1
    }
}

// ---------------------------------------------------------------------------
// Kernel 2: bf16 mma.sync GEMM 16384x256 @ (256x256)^T, ldmatrix fragments,
// fused softplus epilogue + row sums + block reduce + last-block final mean.
// Block: 128 rows x 256 cols, 512 threads = 16 warps (4x4), warp tile 32x64.
// ---------------------------------------------------------------------------
#define SM_ADJ  0                  // 256 f32
#define SM_RED  1024               // 128*4 f32
#define SM_RED2 3072               // 128 f32
#define SM_A    4096               // 128 rows * 528B = 67584
#define SM_B    71680              // 256 rows * 528B = 135168
#define SM_TOT  206848
#define NBLK    (BATCH / 128)      // 128

__global__ void __launch_bounds__(512)
sampled_gemm_kernel(float* __restrict__ d_out, int out_idx)
{
    extern __shared__ char smem[];
    uint32_t sb = smem_to_u32(smem);
    float* adjs = (float*)(smem + SM_ADJ);
    float* red  = (float*)(smem + SM_RED);
    float* red2 = (float*)(smem + SM_RED2);
    __shared__ unsigned s_last;

    const int t    = threadIdx.x;
    const int wid  = t >> 5;
    const int lane = t & 31;
    const int rb   = blockIdx.x * 128;

    // ---- load A tile: 4096 uint4 (8/thread) ----
    {
        const uint4* src = (const uint4*)(g_embed_bf + (size_t)rb * EMB);
        #pragma unroll
        for (int i = 0; i < 8; i++) {
            int idx = t + 512 * i;
            int r = idx >> 5, c = idx & 31;
            *(uint4*)(smem + SM_A + r * 528 + c * 16) = src[idx];
        }
    }
    // ---- load B: 8192 uint4 (16/thread) ----
    {
        const uint4* src = (const uint4*)g_sw;
        #pragma unroll
        for (int i = 0; i < 16; i++) {
            int idx = t + 512 * i;
            int r = idx >> 5, c = idx & 31;
            *(uint4*)(smem + SM_B + r * 528 + c * 16) = src[idx];
        }
    }
    if (t < NS) adjs[t] = g_adj[t];
    __syncthreads();

    // ---- GEMM mainloop: warp tile 32(m) x 64(n), 16 k-steps ----
    const int warp_m = (wid >> 2) * 32;
    const int warp_n = (wid & 3) * 64;
    const int group  = lane >> 2;
    const int tig    = lane & 3;

    float c[2][8][4];
    #pragma unroll
    for (int mt = 0; mt < 2; mt++)
        #pragma unroll
        for (int nt = 0; nt < 8; nt++)
            #pragma unroll
            for (int q = 0; q < 4; q++) c[mt][nt][q] = 0.0f;

    const uint32_t aA = sb + SM_A
        + (uint32_t)((warp_m + (lane & 15)) * 528 + (lane >> 4) * 16);
    const uint32_t aB = sb + SM_B
        + (uint32_t)((warp_n + ((lane >> 4) * 8) + (lane & 7)) * 528
                     + (((lane >> 3) & 1) * 16));

    #pragma unroll
    for (int kk = 0; kk < 16; kk++) {
        const uint32_t kb = kk * 32;   // 16 bf16 = 32 bytes
        uint32_t a[2][4], b[8][2];
        #pragma unroll
        for (int mt = 0; mt < 2; mt++)
            LDSM_X4(a[mt][0], a[mt][1], a[mt][2], a[mt][3],
                    aA + mt * 16 * 528 + kb);
        #pragma unroll
        for (int p = 0; p < 4; p++)
            LDSM_X4(b[2*p][0], b[2*p][1], b[2*p+1][0], b[2*p+1][1],
                    aB + p * 16 * 528 + kb);
        #pragma unroll
        for (int mt = 0; mt < 2; mt++)
            #pragma unroll
            for (int nt = 0; nt < 8; nt++)
                asm volatile(
                    "mma.sync.aligned.m16n8k16.row.col.f32.bf16.bf16.f32 "
                    "{%0,%1,%2,%3}, {%4,%5,%6,%7}, {%8,%9}, {%0,%1,%2,%3};"
                    : "+f"(c[mt][nt][0]), "+f"(c[mt][nt][1]),
                      "+f"(c[mt][nt][2]), "+f"(c[mt][nt][3])
                    : "r"(a[mt][0]), "r"(a[mt][1]), "r"(a[mt][2]), "r"(a[mt][3]),
                      "r"(b[nt][0]), "r"(b[nt][1]));
    }

    // ---- epilogue: softplus + row sums ----
    float rs[2][2] = {{0.f, 0.f}, {0.f, 0.f}};
    #pragma unroll
    for (int mt = 0; mt < 2; mt++) {
        #pragma unroll
        for (int nt = 0; nt < 8; nt++) {
            int n0 = warp_n + nt * 8 + tig * 2;
            float adj0 = adjs[n0], adj1 = adjs[n0 + 1];
            rs[mt][0] += softplus0(c[mt][nt][0] + adj0)
                       + softplus0(c[mt][nt][1] + adj1);
            rs[mt][1] += softplus0(c[mt][nt][2] + adj0)
                       + softplus0(c[mt][nt][3] + adj1);
        }
    }
    #pragma unroll
    for (int mt = 0; mt < 2; mt++)
        #pragma unroll
        for (int h = 0; h < 2; h++) {
            rs[mt][h] += __shfl_xor_sync(0xffffffffu, rs[mt][h], 1);
            rs[mt][h] += __shfl_xor_sync(0xffffffffu, rs[mt][h], 2);
        }
    if (tig == 0) {
        int wc = wid & 3;
        red[(warp_m + group)      * 4 + wc] = rs[0][0];
        red[(warp_m + group + 8)  * 4 + wc] = rs[0][1];
        red[(warp_m + group + 16) * 4 + wc] = rs[1][0];
        red[(warp_m + group + 24) * 4 + wc] = rs[1][1];
    }
    __syncthreads();

    if (t < 128)
        red2[t] = red[t * 4] + red[t * 4 + 1] + red[t * 4 + 2] + red[t * 4 + 3]
                + g_rowsum[rb + t];
    __syncthreads();
    #pragma unroll
    for (int o = 64; o > 0; o >>= 1) {
        if (t < o) red2[t] += red2[t + o];
        __syncthreads();
    }

    // ---- publish partial, elect last block to produce the final mean ----
    if (t == 0) {
        g_partial[blockIdx.x] = red2[0];
        __threadfence();
        unsigned my = atomicAdd(&g_ticket, 1u);
        s_last = (my == NBLK - 1) ? 1u : 0u;
    }
    __syncthreads();

    if (s_last) {
        __threadfence();                        // see all g_partial writes
        if (t < NBLK) red2[t] = g_partial[t];   // fixed order -> deterministic
        __syncthreads();
        #pragma unroll
        for (int o = 64; o > 0; o >>= 1) {
            if (t < o) red2[t] += red2[t + o];
            __syncthreads();
        }
        if (t == 0) {
            d_out[out_idx] = red2[0] / (float)BATCH;
            g_ticket = 0;                       // self-reset for graph replay
        }
    }
}

// ---------------------------------------------------------------------------
// Launch
// ---------------------------------------------------------------------------
extern "C" void kernel_launch(void* const* d_in, const int* in_sizes, int n_in,
                              void* d_out, int out_size)
{
    const float* embeddings = (const float*)d_in[0];
    const float* nce_w      = (const float*)d_in[1];
    const float* nce_b      = (const float*)d_in[2];
    const void*  inputs     = d_in[3];
    const void*  labels     = d_in[4];
    const void*  sids       = d_in[5];
    float*       out        = (float*)d_out;

    int use_dout = (out_size >= BATCH * EMB + 1) ? 1 : 0;

    static int smem_set = 0;
    if (!smem_set) {
        cudaFuncSetAttribute(sampled_gemm_kernel,
                             cudaFuncAttributeMaxDynamicSharedMemorySize,
                             SM_TOT);
        smem_set = 1;
    }

    gather_prep_kernel<<<GATHER_BLOCKS + PREP_BLOCKS, 256>>>(
        embeddings, nce_w, nce_b, inputs, labels, sids, out, use_dout);

    sampled_gemm_kernel<<<NBLK, 512, SM_TOT>>>(out, out_size - 1);
}

// round 13
// speedup vs baseline: 1.6365x; 1.0702x over previous
#include <cuda_runtime.h>
#include <cuda_bf16.h>
#include <math.h>
#include <stdint.h>

#define VOCAB   100000
#define EMB     256
#define NS      256
#define BATCH   16384

// ---------------------------------------------------------------------------
// Device globals (static scratch — no runtime allocation)
// ---------------------------------------------------------------------------
__device__ float          g_rowsum[BATCH];          // true-label xent per row
__device__ float          g_scratch[BATCH * EMB];   // fallback embed buffer
__device__ __nv_bfloat16  g_embed_bf[BATCH * EMB];  // bf16 embed (GEMM A)
__device__ __nv_bfloat16  g_sw[NS * EMB];           // bf16 sampled weights (GEMM B)
__device__ float          g_adj[NS];                // bias - log(NS*prob)
__device__ float          g_partial[512];           // per-CTA loss partials
__device__ unsigned int   g_ticket;                 // last-block election (self-reset)

// ---------------------------------------------------------------------------
// Helpers
// ---------------------------------------------------------------------------
__device__ __forceinline__ uint32_t smem_to_u32(const void* p)
{
    uint32_t a;
    asm("{ .reg .u64 t; cvta.to.shared.u64 t, %1; cvt.u32.u64 %0, t; }"
        : "=r"(a) : "l"(p));
    return a;
}

// jnp int64 silently becomes int32 unless x64 enabled; detect cheaply.
__device__ __forceinline__ int detect_is64(const int* ids)
{
    int is64 = 1;
    #pragma unroll
    for (int k = 0; k < 16; k++)
        if (ids[2 * k + 1] != 0) { is64 = 0; break; }
    return is64;
}

__device__ __forceinline__ int load_id(const void* p, int i, int is64)
{
    if (is64) return (int)((const long long*)p)[i];
    return ((const int*)p)[i];
}

__device__ __forceinline__ float log_uniform_adj(int id)
{
    const float inv_log_range = 1.0f / logf((float)VOCAB + 1.0f);
    float lp = (logf((float)id + 2.0f) - logf((float)id + 1.0f)) * inv_log_range;
    return logf((float)NS * lp);
}

// fast softplus(x) = max(x,0) + log(1 + exp(-|x|))   (xent label = 0)
__device__ __forceinline__ float softplus0(float x)
{
    return fmaxf(x, 0.0f) + __logf(1.0f + __expf(-fabsf(x)));
}

#define LDSM_X4(r0, r1, r2, r3, addr) \
    asm volatile("ldmatrix.sync.aligned.m8n8.x4.shared.b16 {%0,%1,%2,%3}, [%4];" \
                 : "=r"(r0), "=r"(r1), "=r"(r2), "=r"(r3) : "r"(addr))

// ---------------------------------------------------------------------------
// Kernel 1 (combined): blocks [0, 2048) gather embed rows + true-label xent;
// blocks [2048, 2080) prep sampled weights (bf16) + adjustment terms.
// ---------------------------------------------------------------------------
#define GATHER_BLOCKS (BATCH / 8)        // 2048
#define PREP_BLOCKS   (NS / 8)           // 32

__global__ void gather_prep_kernel(const float* __restrict__ embeddings,
                                   const float* __restrict__ nce_w,
                                   const float* __restrict__ nce_b,
                                   const void*  __restrict__ inputs,
                                   const void*  __restrict__ labels,
                                   const void*  __restrict__ sids,
                                   float*       __restrict__ d_out,
                                   int use_dout)
{
    const int lane = threadIdx.x & 31;

    if (blockIdx.x >= GATHER_BLOCKS) {
        // ---------------- prep branch: sampled weights -> bf16 + adj --------
        __shared__ int sh64p;
        if (threadIdx.x == 0) sh64p = detect_is64((const int*)sids);
        __syncthreads();
        int row = (blockIdx.x - GATHER_BLOCKS) * 8 + (threadIdx.x >> 5);
        int id  = load_id(sids, row, sh64p);

        const float4* w4 = (const float4*)(nce_w + (size_t)id * EMB);
        float4 v0 = w4[lane];
        float4 v1 = w4[lane + 32];

        __nv_bfloat162 p0 = __floats2bfloat162_rn(v0.x, v0.y);
        __nv_bfloat162 p1 = __floats2bfloat162_rn(v0.z, v0.w);
        __nv_bfloat162 p2 = __floats2bfloat162_rn(v1.x, v1.y);
        __nv_bfloat162 p3 = __floats2bfloat162_rn(v1.z, v1.w);
        uint2* dst = (uint2*)(g_sw + (size_t)row * EMB);
        uint2 a; a.x = *(uint32_t*)&p0; a.y = *(uint32_t*)&p1;
        uint2 b; b.x = *(uint32_t*)&p2; b.y = *(uint32_t*)&p3;
        dst[lane]      = a;
        dst[lane + 32] = b;

        if (lane == 0)
            g_adj[row] = nce_b[id] - log_uniform_adj(id);
        return;
    }

    // ---------------- gather branch ----------------------------------------
    __shared__ int sh64;
    if (threadIdx.x == 0) sh64 = detect_is64((const int*)inputs);
    __syncthreads();
    const int is64 = sh64;

    int warp = (blockIdx.x * blockDim.x + threadIdx.x) >> 5;

    float* embed_out = use_dout ? d_out : g_scratch;

    int id  = load_id(inputs, warp, is64);
    int lab = load_id(labels, warp, is64);

    const float4* e4 = (const float4*)(embeddings + (size_t)id  * EMB);
    const float4* w4 = (const float4*)(nce_w      + (size_t)lab * EMB);
    float4*       o4 = (float4*)(embed_out + (size_t)warp * EMB);

    float4 a0 = e4[lane];
    float4 a1 = e4[lane + 32];
    float4 b0 = w4[lane];
    float4 b1 = w4[lane + 32];
    o4[lane]      = a0;
    o4[lane + 32] = a1;

    {
        __nv_bfloat162 p0 = __floats2bfloat162_rn(a0.x, a0.y);
        __nv_bfloat162 p1 = __floats2bfloat162_rn(a0.z, a0.w);
        __nv_bfloat162 p2 = __floats2bfloat162_rn(a1.x, a1.y);
        __nv_bfloat162 p3 = __floats2bfloat162_rn(a1.z, a1.w);
        uint2* dst = (uint2*)(g_embed_bf + (size_t)warp * EMB);
        uint2 v0; v0.x = *(uint32_t*)&p0; v0.y = *(uint32_t*)&p1;
        uint2 v1; v1.x = *(uint32_t*)&p2; v1.y = *(uint32_t*)&p3;
        dst[lane]      = v0;
        dst[lane + 32] = v1;
    }

    float p = a0.x * b0.x + a0.y * b0.y + a0.z * b0.z + a0.w * b0.w
            + a1.x * b1.x + a1.y * b1.y + a1.z * b1.z + a1.w * b1.w;
    #pragma unroll
    for (int o = 16; o > 0; o >>= 1)
        p += __shfl_xor_sync(0xffffffffu, p, o);

    if (lane == 0) {
        float x = p + nce_b[lab] - log_uniform_adj(lab);
        g_rowsum[warp] = softplus0(-x);   // label = 1
    }
}

// ---------------------------------------------------------------------------
// Kernel 2: bf16 mma.sync GEMM, CTA tile 64 rows x 128 cols (N split in 2),
// ~102KB smem -> 2 CTAs/SM for phase overlap. 256 threads = 8 warps (2m x 4n),
// warp tile 32x32. Fused softplus epilogue + row sums + last-block mean.
// grid = 256 row-blocks x 2 N-halves = 512 CTAs.
// ---------------------------------------------------------------------------
#define SM_ADJ   0                 // 128 f32 (this half's adj)
#define SM_RED   512               // 64*4 f32
#define SM_RED2  1536              // 64 f32
#define SM_RED3  1792              // 256 f32 (final reduce, last block only)
#define SM_A     2816              // 64 rows * 528B = 33792
#define SM_B     36608             // 128 rows * 528B = 67584
#define SM_TOT   104192
#define NBLK2    512

__global__ void __launch_bounds__(256)
sampled_gemm_kernel(float* __restrict__ d_out, int out_idx)
{
    extern __shared__ char smem[];
    uint32_t sb = smem_to_u32(smem);
    float* adjs = (float*)(smem + SM_ADJ);
    float* red  = (float*)(smem + SM_RED);
    float* red2 = (float*)(smem + SM_RED2);
    float* red3 = (float*)(smem + SM_RED3);
    __shared__ unsigned s_last;

    const int t    = threadIdx.x;
    const int wid  = t >> 5;
    const int lane = t & 31;
    const int rblk = blockIdx.x >> 1;      // row block (0..255)
    const int half = blockIdx.x & 1;       // N half (0..1)
    const int rb   = rblk * 64;

    // ---- load A tile: 64 rows x 256 bf16 = 2048 uint4 (8/thread) ----
    {
        const uint4* src = (const uint4*)(g_embed_bf + (size_t)rb * EMB);
        #pragma unroll
        for (int i = 0; i < 8; i++) {
            int idx = t + 256 * i;
            int r = idx >> 5, c = idx & 31;
            *(uint4*)(smem + SM_A + r * 528 + c * 16) = src[idx];
        }
    }
    // ---- load B half: 128 rows x 256 bf16 = 4096 uint4 (16/thread) ----
    {
        const uint4* src = (const uint4*)(g_sw + (size_t)(half * 128) * EMB);
        #pragma unroll
        for (int i = 0; i < 16; i++) {
            int idx = t + 256 * i;
            int r = idx >> 5, c = idx & 31;
            *(uint4*)(smem + SM_B + r * 528 + c * 16) = src[idx];
        }
    }
    if (t < 128) adjs[t] = g_adj[half * 128 + t];
    __syncthreads();

    // ---- GEMM mainloop: warp tile 32(m) x 32(n), 16 k-steps ----
    const int warp_m = (wid >> 2) * 32;    // 0, 32
    const int warp_n = (wid & 3) * 32;     // 0, 32, 64, 96
    const int group  = lane >> 2;
    const int tig    = lane & 3;

    float c[2][4][4];
    #pragma unroll
    for (int mt = 0; mt < 2; mt++)
        #pragma unroll
        for (int nt = 0; nt < 4; nt++)
            #pragma unroll
            for (int q = 0; q < 4; q++) c[mt][nt][q] = 0.0f;

    // ldmatrix lane-address bases (pattern validated rounds 8-10)
    const uint32_t aA = sb + SM_A
        + (uint32_t)((warp_m + (lane & 15)) * 528 + (lane >> 4) * 16);
    const uint32_t aB = sb + SM_B
        + (uint32_t)((warp_n + ((lane >> 4) * 8) + (lane & 7)) * 528
                     + (((lane >> 3) & 1) * 16));

    #pragma unroll
    for (int kk = 0; kk < 16; kk++) {
        const uint32_t kb = kk * 32;   // 16 bf16 = 32 bytes
        uint32_t a[2][4], b[4][2];
        #pragma unroll
        for (int mt = 0; mt < 2; mt++)
            LDSM_X4(a[mt][0], a[mt][1], a[mt][2], a[mt][3],
                    aA + mt * 16 * 528 + kb);
        #pragma unroll
        for (int p = 0; p < 2; p++)
            LDSM_X4(b[2*p][0], b[2*p][1], b[2*p+1][0], b[2*p+1][1],
                    aB + p * 16 * 528 + kb);
        #pragma unroll
        for (int mt = 0; mt < 2; mt++)
            #pragma unroll
            for (int nt = 0; nt < 4; nt++)
                asm volatile(
                    "mma.sync.aligned.m16n8k16.row.col.f32.bf16.bf16.f32 "
                    "{%0,%1,%2,%3}, {%4,%5,%6,%7}, {%8,%9}, {%0,%1,%2,%3};"
                    : "+f"(c[mt][nt][0]), "+f"(c[mt][nt][1]),
                      "+f"(c[mt][nt][2]), "+f"(c[mt][nt][3])
                    : "r"(a[mt][0]), "r"(a[mt][1]), "r"(a[mt][2]), "r"(a[mt][3]),
                      "r"(b[nt][0]), "r"(b[nt][1]));
    }

    // ---- epilogue: softplus + row sums (this half's 128 cols) ----
    float rs[2][2] = {{0.f, 0.f}, {0.f, 0.f}};
    #pragma unroll
    for (int mt = 0; mt < 2; mt++) {
        #pragma unroll
        for (int nt = 0; nt < 4; nt++) {
            int n0 = warp_n + nt * 8 + tig * 2;
            float adj0 = adjs[n0], adj1 = adjs[n0 + 1];
            rs[mt][0] += softplus0(c[mt][nt][0] + adj0)
                       + softplus0(c[mt][nt][1] + adj1);
            rs[mt][1] += softplus0(c[mt][nt][2] + adj0)
                       + softplus0(c[mt][nt][3] + adj1);
        }
    }
    #pragma unroll
    for (int mt = 0; mt < 2; mt++)
        #pragma unroll
        for (int h = 0; h < 2; h++) {
            rs[mt][h] += __shfl_xor_sync(0xffffffffu, rs[mt][h], 1);
            rs[mt][h] += __shfl_xor_sync(0xffffffffu, rs[mt][h], 2);
        }
    if (tig == 0) {
        int wc = wid & 3;
        red[(warp_m + group)      * 4 + wc] = rs[0][0];
        red[(warp_m + group + 8)  * 4 + wc] = rs[0][1];
        red[(warp_m + group + 16) * 4 + wc] = rs[1][0];
        red[(warp_m + group + 24) * 4 + wc] = rs[1][1];
    }
    __syncthreads();

    // per-row partial; half 0 also adds the true-label xent
    if (t < 64) {
        float s = red[t * 4] + red[t * 4 + 1] + red[t * 4 + 2] + red[t * 4 + 3];
        if (half == 0) s += g_rowsum[rb + t];
        red2[t] = s;
    }
    __syncthreads();
    #pragma unroll
    for (int o = 32; o > 0; o >>= 1) {
        if (t < o) red2[t] += red2[t + o];
        __syncthreads();
    }

    // ---- publish partial; last block produces the final mean ----
    if (t == 0) {
        g_partial[blockIdx.x] = red2[0];
        __threadfence();
        unsigned my = atomicAdd(&g_ticket, 1u);
        s_last = (my == NBLK2 - 1) ? 1u : 0u;
    }
    __syncthreads();

    if (s_last) {
        __threadfence();                      // see all g_partial writes
        red3[t] = g_partial[t] + g_partial[t + 256];   // fixed order
        __syncthreads();
        #pragma unroll
        for (int o = 128; o > 0; o >>= 1) {
            if (t < o) red3[t] += red3[t + o];
            __syncthreads();
        }
        if (t == 0) {
            d_out[out_idx] = red3[0] / (float)BATCH;
            g_ticket = 0;                     // self-reset for graph replay
        }
    }
}

// ---------------------------------------------------------------------------
// Launch
// ---------------------------------------------------------------------------
extern "C" void kernel_launch(void* const* d_in, const int* in_sizes, int n_in,
                              void* d_out, int out_size)
{
    const float* embeddings = (const float*)d_in[0];
    const float* nce_w      = (const float*)d_in[1];
    const float* nce_b      = (const float*)d_in[2];
    const void*  inputs     = d_in[3];
    const void*  labels     = d_in[4];
    const void*  sids       = d_in[5];
    float*       out        = (float*)d_out;

    int use_dout = (out_size >= BATCH * EMB + 1) ? 1 : 0;

    static int smem_set = 0;
    if (!smem_set) {
        cudaFuncSetAttribute(sampled_gemm_kernel,
                             cudaFuncAttributeMaxDynamicSharedMemorySize,
                             SM_TOT);
        smem_set = 1;
    }

    gather_prep_kernel<<<GATHER_BLOCKS + PREP_BLOCKS, 256>>>(
        embeddings, nce_w, nce_b, inputs, labels, sids, out, use_dout);

    sampled_gemm_kernel<<<NBLK2, 256, SM_TOT>>>(out, out_size - 1);
}